// round 8
// baseline (speedup 1.0000x reference)
#include <cuda_runtime.h>
#include <cstdint>
#include <math.h>

#define H    8192      // DIM_HIDDEN
#define S    4096      // DIM_SOL (steps)
#define CTX  4096      // DIM_CONTEXT
#define CSZ  8         // cluster size
#define NWW  8         // worker warps per CTA
#define WTH  256       // worker threads per CTA
#define EPT  4         // hidden elems per worker thread (256*4*8 = 8192)
#define TPB  288       // 8 worker warps + logp warp (wid 8)
#define RDEP 4         // recv ring depth

// ---------------- device scratch (static, no allocs) ----------------
__device__ float  g_Wt[(size_t)S * H];   // transposed W[:, CTX:]
__device__ float  g_a0[H];               // a0 = c + W[:, :CTX] @ context
__device__ float2 g_thr2[S];             // (t_hi, t_lo) two-float logit(u_i)

// ---------------- helpers ----------------
__device__ __forceinline__ float sigmoidf_fast(float x) {
    return __fdividef(1.0f, 1.0f + __expf(-x));
}
__device__ __forceinline__ float softplusf(float y) {
    float t = fabsf(y);
    float r = log1pf(__expf(-t));
    return (y > 0.f) ? (y + r) : r;
}
__device__ __forceinline__ unsigned cluster_rank() {
    unsigned r; asm("mov.u32 %0, %%cluster_ctarank;" : "=r"(r)); return r;
}
__device__ __forceinline__ uint32_t smem_u32(const void* p) {
    return (uint32_t)__cvta_generic_to_shared(p);
}
__device__ __forceinline__ void remote_store64(uint32_t laddr, unsigned rank, unsigned long long v) {
    uint32_t raddr;
    asm volatile("mapa.shared::cluster.u32 %0, %1, %2;" : "=r"(raddr) : "r"(laddr), "r"(rank));
    asm volatile("st.relaxed.cluster.shared::cluster.b64 [%0], %1;" :: "r"(raddr), "l"(v) : "memory");
}
__device__ __forceinline__ void cluster_barrier() {
    asm volatile("barrier.cluster.arrive.aligned;" ::: "memory");
    asm volatile("barrier.cluster.wait.aligned;"   ::: "memory");
}
// interleaved dual warp-sum: two independent 5-level SHFL chains pipelined
__device__ __forceinline__ void bfly2(float& x, float& y) {
    #pragma unroll
    for (int o = 16; o > 0; o >>= 1) {
        x += __shfl_xor_sync(0xffffffffu, x, o);
        y += __shfl_xor_sync(0xffffffffu, y, o);
    }
}
// threshold compare: s = (x > t) with t = t_hi + t_lo (x is exact fp32)
__device__ __forceinline__ bool thr_cmp(float x, float2 t) {
    return (x > t.x) || ((x == t.x) && (t.y < 0.f));
}

// ---------------- init kernel 1: a0 = c + W[:, :CTX] @ context ----------------
__global__ void gemv_kernel(const float* __restrict__ W,
                            const float* __restrict__ ctxv,
                            const float* __restrict__ c) {
    __shared__ float sred[256];
    int r = blockIdx.x;
    const float* row = W + (size_t)r * (CTX + S);
    float acc = 0.f;
    for (int k = threadIdx.x; k < CTX; k += 256)
        acc += row[k] * ctxv[k];
    sred[threadIdx.x] = acc;
    __syncthreads();
    for (int off = 128; off > 0; off >>= 1) {
        if (threadIdx.x < off) sred[threadIdx.x] += sred[threadIdx.x + off];
        __syncthreads();
    }
    if (threadIdx.x == 0) g_a0[r] = c[r] + sred[0];
}

// ---------------- init kernel 2: transpose W[:, CTX:] -> g_Wt ----------------
__global__ void transpose_kernel(const float* __restrict__ W) {
    __shared__ float tile[32][33];
    int i0 = blockIdx.x * 32;   // step index base
    int j0 = blockIdx.y * 32;   // hidden index base
    int tx = threadIdx.x;
    #pragma unroll
    for (int t = 0; t < 4; t++) {
        int ty = threadIdx.y + t * 8;
        tile[ty][tx] = W[(size_t)(j0 + ty) * (CTX + S) + CTX + i0 + tx];
    }
    __syncthreads();
    #pragma unroll
    for (int t = 0; t < 4; t++) {
        int ty = threadIdx.y + t * 8;
        g_Wt[(size_t)(i0 + ty) * H + j0 + tx] = tile[tx][ty];
    }
}

// ---------------- init kernel 3: two-float thresholds ----------------
__global__ void thr_kernel(const float* __restrict__ u) {
    int i = blockIdx.x * 256 + threadIdx.x;
    if (i < S) {
        double ud = (double)u[i];
        double t  = log(ud / (1.0 - ud));
        float hi  = (float)t;
        float lo  = (float)(t - (double)hi);
        g_thr2[i] = make_float2(hi, lo);
    }
}

// ---------------- main sequential kernel: 8-CTA cluster ----------------
// recv layout per ring slot: [0..63]   = e0 words (srcCTA*8 + warp), tag in hi32
//                            [64..127] = e1 words (same index + 64)
__global__ void __cluster_dims__(CSZ, 1, 1) __launch_bounds__(TPB, 1)
nade_kernel(const float* __restrict__ V,
            const float* __restrict__ b,
            float* __restrict__ out,
            int out_size) {
    __shared__ unsigned long long recv[RDEP][128];  // worker-pair broadcast slots
    __shared__ unsigned long long xw[S];            // x per step (tagged) — no reuse

    const unsigned rank = cluster_rank();
    const int tid  = threadIdx.x;
    const int wid  = tid >> 5;
    const int lane = tid & 31;

    for (int k = tid; k < RDEP * 128; k += TPB)
        ((unsigned long long*)recv)[k] = 0xFFFFFFFF00000000ULL;
    for (int k = tid; k < S; k += TPB)
        xw[k] = 0xFFFFFFFF00000000ULL;
    __syncthreads();
    cluster_barrier();   // everyone's recv initialized before any remote store

    volatile unsigned long long* xwv = xw;

    if (wid < NWW) {
        // ================= worker warps (also decide) =================
        const int base  = (int)rank * (WTH * EPT) + tid;   // + e*WTH
        const int slotA = (int)rank * 8 + wid;             // e0 slot index
        const bool xwriter = (rank == 0 && wid == 0 && lane == 0);

        float a[EPT], h[EPT], h1[EPT];
        // deep register prefetch: distance 4
        float wPrev[EPT], wC[EPT], wN1[EPT], wN2[EPT], wN3[EPT];
        float vC[EPT], vN1[EPT], vN2[EPT], vN3[EPT];

        #pragma unroll
        for (int e = 0; e < EPT; e++) {
            int j   = base + e * WTH;
            a[e]    = g_a0[j];
            h[e]    = sigmoidf_fast(a[e]);
            wPrev[e]= g_Wt[j];                          // W_0
            wC[e]   = g_Wt[(size_t)1 * H + j];          // W_1
            wN1[e]  = g_Wt[(size_t)2 * H + j];          // W_2
            wN2[e]  = g_Wt[(size_t)3 * H + j];          // W_3
            wN3[e]  = g_Wt[(size_t)4 * H + j];          // W_4
            vC[e]   = V[(size_t)2 * H + j];             // V_2
            vN1[e]  = V[(size_t)3 * H + j];             // V_3
            vN2[e]  = V[(size_t)4 * H + j];             // V_4
            vN3[e]  = V[(size_t)5 * H + j];             // V_5
        }

        // rolling b/threshold prefetch (used when deciding step p-2 at iter p)
        float  bc = b[0],      bn = b[1];
        float2 tc = g_thr2[0], tn = g_thr2[1];
        unsigned sprev = 0;

        // send helper: lanes 0-15 broadcast the tagged pair to all 8 CTAs
        auto send_pair = [&](int p, float e0, float e1) {
            if (lane < 16) {
                float val = (lane < 8) ? e0 : e1;
                int   slot = (lane < 8) ? slotA : (64 + slotA);
                unsigned long long pk =
                    ((unsigned long long)(unsigned)p << 32) |
                    (unsigned long long)__float_as_uint(val);
                remote_store64(smem_u32(&recv[p & (RDEP - 1)][slot]), (unsigned)(lane & 7), pk);
            }
        };

        // poll + reduce both branch sums for step q (identical in all warps/CTAs)
        auto recv_reduce = [&](int q, float& D0, float& D1) {
            const unsigned want = (unsigned)q;
            volatile unsigned long long* rv = &recv[q & (RDEP - 1)][0];
            unsigned long long A0, A1, B0, B1;
            for (;;) {
                A0 = rv[2 * lane];
                A1 = rv[2 * lane + 1];
                B0 = rv[64 + 2 * lane];
                B1 = rv[64 + 2 * lane + 1];
                if (((unsigned)(A0 >> 32) == want) & ((unsigned)(A1 >> 32) == want) &
                    ((unsigned)(B0 >> 32) == want) & ((unsigned)(B1 >> 32) == want))
                    break;
            }
            float d0 = __uint_as_float((unsigned)A0) + __uint_as_float((unsigned)A1);
            float d1 = __uint_as_float((unsigned)B0) + __uint_as_float((unsigned)B1);
            bfly2(d0, d1);
            D0 = d0; D1 = d1;
        };

        // prologue: pair(0) = V_0 . h (both branches equal); pair(1) over s_0
        {
            float e0 = 0.f, dummy = 0.f;
            #pragma unroll
            for (int e = 0; e < EPT; e++)
                e0 = fmaf(V[base + e * WTH], h[e], e0);
            bfly2(e0, dummy);
            send_pair(0, e0, e0);
        }
        {
            float e0 = 0.f, e1 = 0.f;
            #pragma unroll
            for (int e = 0; e < EPT; e++) {
                h1[e] = sigmoidf_fast(a[e] + wPrev[e]);   // sigma(a0 + W_0)
                float v1 = V[(size_t)1 * H + base + e * WTH];
                e0 = fmaf(v1, h[e],  e0);
                e1 = fmaf(v1, h1[e], e1);
            }
            bfly2(e0, e1);
            send_pair(1, e0, e1);
        }

        #pragma unroll 4
        for (int p = 2; p < S; p++) {
            // far-ahead prefetches (fly during the recv wait)
            int pw = (p + 3 < S) ? p + 3 : S - 1;   // W row used at iter p+4
            int pv = (p + 4 < S) ? p + 4 : S - 1;   // V row used at iter p+4
            float wf[EPT], vf[EPT];
            #pragma unroll
            for (int e = 0; e < EPT; e++) {
                wf[e] = g_Wt[(size_t)pw * H + base + e * WTH];
                vf[e] = V[(size_t)pv * H + base + e * WTH];
            }
            float  bf = b[p];          // for deciding step p at iter p+2
            float2 tf = g_thr2[p];

            // ---- decide step p-2 locally ----
            float D0, D1;
            recv_reduce(p - 2, D0, D1);
            float x = bc + (sprev ? D1 : D0);
            bool  s = thr_cmp(x, tc);
            sprev = (unsigned)s;
            if (xwriter)
                xwv[p - 2] = ((unsigned long long)(unsigned)(p - 2) << 32) |
                             (unsigned long long)__float_as_uint(x);

            // ---- commit, speculate, dot ----
            float sm = (float)s;
            float e0 = 0.f, e1 = 0.f;
            #pragma unroll
            for (int e = 0; e < EPT; e++) {
                a[e] = fmaf(sm, wPrev[e], a[e]);
                h[e] = s ? h1[e] : h[e];
                h1[e] = sigmoidf_fast(a[e] + wC[e]);   // branch s_{p-1}=1
                e0 = fmaf(vC[e], h[e],  e0);
                e1 = fmaf(vC[e], h1[e], e1);
            }
            bfly2(e0, e1);
            send_pair(p, e0, e1);

            // rotate buffers
            #pragma unroll
            for (int e = 0; e < EPT; e++) {
                wPrev[e] = wC[e]; wC[e] = wN1[e]; wN1[e] = wN2[e]; wN2[e] = wN3[e]; wN3[e] = wf[e];
                vC[e] = vN1[e]; vN1[e] = vN2[e]; vN2[e] = vN3[e]; vN3[e] = vf[e];
            }
            bc = bn; bn = bf; tc = tn; tn = tf;
        }

        // ---- tail: decide steps S-2 and S-1 (x needed for out[]) ----
        if (rank == 0 && wid == 0) {
            #pragma unroll
            for (int q = S - 2; q < S; q++) {
                float D0, D1;
                recv_reduce(q, D0, D1);
                float x = bc + (sprev ? D1 : D0);
                bool  s = thr_cmp(x, tc);
                sprev = (unsigned)s;
                if (lane == 0)
                    xwv[q] = ((unsigned long long)(unsigned)q << 32) |
                             (unsigned long long)__float_as_uint(x);
                bc = bn; tc = tn;
            }
        }
    } else {
        // ================= logp/output warp (rank 0, lane 0 only) =================
        if (rank == 0 && lane == 0) {
            float2 tc = g_thr2[0], tn = g_thr2[1];
            double lp = 0.0;
            for (int i = 0; i < S; i++) {
                unsigned long long xv;
                do { xv = xwv[i]; } while ((unsigned)(xv >> 32) != (unsigned)i);
                float x = __uint_as_float((unsigned)xv);
                bool  s = thr_cmp(x, tc);
                out[i] = s ? 1.0f : 0.0f;
                if (i < S - 2)
                    lp -= (double)(s ? softplusf(-x) : softplusf(x));
                int ip = (i + 2 < S) ? i + 2 : S - 1;
                float2 tf = g_thr2[ip];
                tc = tn; tn = tf;
            }
            out[S] = (float)lp;
            for (int k = S + 1; k < out_size; k++) out[k] = 0.f;
        }
    }

    cluster_barrier();   // no CTA exits while peers may still store to its smem
}

// ---------------- launch ----------------
extern "C" void kernel_launch(void* const* d_in, const int* in_sizes, int n_in,
                              void* d_out, int out_size) {
    const float* ctxv = nullptr;
    const float* u    = nullptr;
    const float* W    = nullptr;
    const float* V    = nullptr;
    const float* b    = nullptr;
    const float* c    = nullptr;

    const int szW = (CTX + S) * H;   // 67108864
    const int szV = S * H;           // 33554432
    int n4seen = 0;
    for (int idx = 0; idx < n_in; idx++) {
        int sz = in_sizes[idx];
        const float* p = (const float*)d_in[idx];
        if (sz == szW)       W = p;
        else if (sz == szV)  V = p;
        else if (sz == H)    c = p;
        else if (sz == S) {
            if      (n4seen == 0) ctxv = p;
            else if (n4seen == 1) u    = p;
            else                  b    = p;
            n4seen++;
        }
    }
    if (!ctxv) ctxv = (const float*)d_in[0];
    if (!u)    u    = (const float*)d_in[1];
    if (!W)    W    = (const float*)d_in[2];
    if (!V)    V    = (const float*)d_in[3];
    if (!b)    b    = (const float*)d_in[4];
    if (!c)    c    = (const float*)d_in[5];

    float* out = (float*)d_out;

    gemv_kernel<<<H, 256>>>(W, ctxv, c);
    transpose_kernel<<<dim3(S / 32, H / 32), dim3(32, 8)>>>(W);
    thr_kernel<<<(S + 255) / 256, 256>>>(u);
    nade_kernel<<<CSZ, TPB>>>(V, b, out, out_size);
}

// round 9
// speedup vs baseline: 3.2849x; 3.2849x over previous
#include <cuda_runtime.h>
#include <cstdint>
#include <math.h>

#define H    8192      // DIM_HIDDEN
#define S    4096      // DIM_SOL (steps)
#define CTX  4096      // DIM_CONTEXT
#define CSZ  8         // cluster size
#define NWW  8         // worker warps per CTA
#define WTH  256       // worker threads per CTA
#define EPT  4         // hidden elems per worker thread (256*4*8 = 8192)
#define TPB  352       // 8 workers + sender(8) + decider(9) + logp(10)
#define RDEP 4         // ring depth

// ---------------- device scratch (static, no allocs) ----------------
__device__ float  g_Wt[(size_t)S * H];   // transposed W[:, CTX:]
__device__ float  g_a0[H];               // a0 = c + W[:, :CTX] @ context
__device__ float2 g_thr2[S];             // (t_hi, t_lo) two-float logit(u_i)

// ---------------- helpers ----------------
__device__ __forceinline__ float sigmoidf_fast(float x) {
    return __fdividef(1.0f, 1.0f + __expf(-x));
}
__device__ __forceinline__ float softplusf(float y) {
    float t = fabsf(y);
    float r = log1pf(__expf(-t));
    return (y > 0.f) ? (y + r) : r;
}
__device__ __forceinline__ unsigned cluster_rank() {
    unsigned r; asm("mov.u32 %0, %%cluster_ctarank;" : "=r"(r)); return r;
}
__device__ __forceinline__ uint32_t smem_u32(const void* p) {
    return (uint32_t)__cvta_generic_to_shared(p);
}
__device__ __forceinline__ void remote_store64(uint32_t laddr, unsigned rank, unsigned long long v) {
    uint32_t raddr;
    asm volatile("mapa.shared::cluster.u32 %0, %1, %2;" : "=r"(raddr) : "r"(laddr), "r"(rank));
    asm volatile("st.relaxed.cluster.shared::cluster.b64 [%0], %1;" :: "r"(raddr), "l"(v) : "memory");
}
__device__ __forceinline__ void cluster_barrier() {
    asm volatile("barrier.cluster.arrive.aligned;" ::: "memory");
    asm volatile("barrier.cluster.wait.aligned;"   ::: "memory");
}
// volatile 16B shared load (tagged-word polling)
__device__ __forceinline__ uint4 lds128v(const void* p) {
    uint4 r;
    asm volatile("ld.volatile.shared.v4.b32 {%0,%1,%2,%3}, [%4];"
                 : "=r"(r.x), "=r"(r.y), "=r"(r.z), "=r"(r.w) : "r"(smem_u32(p)));
    return r;
}
// interleaved dual warp-sum (workers only; off the decision recurrence)
__device__ __forceinline__ void bfly2(float& x, float& y) {
    #pragma unroll
    for (int o = 16; o > 0; o >>= 1) {
        x += __shfl_xor_sync(0xffffffffu, x, o);
        y += __shfl_xor_sync(0xffffffffu, y, o);
    }
}
// threshold compare: s = (x > t) with t = t_hi + t_lo (x is exact fp32)
__device__ __forceinline__ bool thr_cmp(float x, float2 t) {
    return (x > t.x) || ((x == t.x) && (t.y < 0.f));
}

// ---------------- init kernel 1: a0 = c + W[:, :CTX] @ context ----------------
__global__ void gemv_kernel(const float* __restrict__ W,
                            const float* __restrict__ ctxv,
                            const float* __restrict__ c) {
    __shared__ float sred[256];
    int r = blockIdx.x;
    const float* row = W + (size_t)r * (CTX + S);
    float acc = 0.f;
    for (int k = threadIdx.x; k < CTX; k += 256)
        acc += row[k] * ctxv[k];
    sred[threadIdx.x] = acc;
    __syncthreads();
    for (int off = 128; off > 0; off >>= 1) {
        if (threadIdx.x < off) sred[threadIdx.x] += sred[threadIdx.x + off];
        __syncthreads();
    }
    if (threadIdx.x == 0) g_a0[r] = c[r] + sred[0];
}

// ---------------- init kernel 2: transpose W[:, CTX:] -> g_Wt ----------------
__global__ void transpose_kernel(const float* __restrict__ W) {
    __shared__ float tile[32][33];
    int i0 = blockIdx.x * 32;   // step index base
    int j0 = blockIdx.y * 32;   // hidden index base
    int tx = threadIdx.x;
    #pragma unroll
    for (int t = 0; t < 4; t++) {
        int ty = threadIdx.y + t * 8;
        tile[ty][tx] = W[(size_t)(j0 + ty) * (CTX + S) + CTX + i0 + tx];
    }
    __syncthreads();
    #pragma unroll
    for (int t = 0; t < 4; t++) {
        int ty = threadIdx.y + t * 8;
        g_Wt[(size_t)(i0 + ty) * H + j0 + tx] = tile[tx][ty];
    }
}

// ---------------- init kernel 3: two-float thresholds ----------------
__global__ void thr_kernel(const float* __restrict__ u) {
    int i = blockIdx.x * 256 + threadIdx.x;
    if (i < S) {
        double ud = (double)u[i];
        double t  = log(ud / (1.0 - ud));
        float hi  = (float)t;
        float lo  = (float)(t - (double)hi);
        g_thr2[i] = make_float2(hi, lo);
    }
}

// ---------------- main sequential kernel: 8-CTA cluster ----------------
// wp[r][0..7]  = local worker e0 words {tag|val}, [8..15] = e1 words
// slots[r][0..7] = E0 per src CTA, [8..15] = E1 per src CTA
__global__ void __cluster_dims__(CSZ, 1, 1) __launch_bounds__(TPB, 1)
nade_kernel(const float* __restrict__ V,
            const float* __restrict__ b,
            float* __restrict__ out,
            int out_size) {
    __shared__ __align__(16) unsigned long long wp[RDEP][16];
    __shared__ __align__(16) unsigned long long slots[RDEP][16];
    __shared__ unsigned int       dec[RDEP];
    __shared__ unsigned long long xw[S];

    const unsigned rank = cluster_rank();
    const int tid  = threadIdx.x;
    const int wid  = tid >> 5;
    const int lane = tid & 31;

    for (int k = tid; k < RDEP * 16; k += TPB) {
        ((unsigned long long*)wp)[k]    = 0xFFFFFFFF00000000ULL;
        ((unsigned long long*)slots)[k] = 0xFFFFFFFF00000000ULL;
    }
    if (tid < RDEP) dec[tid] = 0xFFFFFFFFu;
    for (int k = tid; k < S; k += TPB)
        xw[k] = 0xFFFFFFFF00000000ULL;
    __syncthreads();
    cluster_barrier();   // all CTAs' slots initialized before any remote store

    volatile unsigned int*       decv = dec;
    volatile unsigned long long* xwv  = xw;

    if (wid < NWW) {
        // ================= worker warps =================
        const int base = (int)rank * (WTH * EPT) + tid;   // + e*WTH
        float a[EPT], h[EPT], h1[EPT];
        // deep register prefetch: distance 4
        float wPrev[EPT], wC[EPT], wN1[EPT], wN2[EPT], wN3[EPT];
        float vC[EPT], vN1[EPT], vN2[EPT], vN3[EPT];

        #pragma unroll
        for (int e = 0; e < EPT; e++) {
            int j   = base + e * WTH;
            a[e]    = g_a0[j];
            h[e]    = sigmoidf_fast(a[e]);
            wPrev[e]= g_Wt[j];                          // W_0
            wC[e]   = g_Wt[(size_t)1 * H + j];          // W_1
            wN1[e]  = g_Wt[(size_t)2 * H + j];          // W_2
            wN2[e]  = g_Wt[(size_t)3 * H + j];          // W_3
            wN3[e]  = g_Wt[(size_t)4 * H + j];          // W_4
            vC[e]   = V[(size_t)2 * H + j];             // V_2
            vN1[e]  = V[(size_t)3 * H + j];             // V_3
            vN2[e]  = V[(size_t)4 * H + j];             // V_4
            vN3[e]  = V[(size_t)5 * H + j];             // V_5
        }

        auto publish = [&](int p, float e0, float e1) {
            if (lane == 0) {
                unsigned long long tg = (unsigned long long)(unsigned)p << 32;
                const int r = p & (RDEP - 1);
                ((volatile unsigned long long*)wp[r])[wid]     = tg | __float_as_uint(e0);
                ((volatile unsigned long long*)wp[r])[8 + wid] = tg | __float_as_uint(e1);
            }
        };

        // prologue: pair(0) = V_0 . h (both equal); pair(1) speculates on s_0
        {
            float e0 = 0.f, dummy = 0.f;
            #pragma unroll
            for (int e = 0; e < EPT; e++)
                e0 = fmaf(V[base + e * WTH], h[e], e0);
            bfly2(e0, dummy);
            publish(0, e0, e0);
        }
        {
            float e0 = 0.f, e1 = 0.f;
            #pragma unroll
            for (int e = 0; e < EPT; e++) {
                h1[e] = sigmoidf_fast(a[e] + wPrev[e]);   // sigma(a0 + W_0)
                float v1 = V[(size_t)1 * H + base + e * WTH];
                e0 = fmaf(v1, h[e],  e0);
                e1 = fmaf(v1, h1[e], e1);
            }
            bfly2(e0, e1);
            publish(1, e0, e1);
        }

        #pragma unroll 4
        for (int p = 2; p < S; p++) {
            // far-ahead prefetches (fly during the dec wait)
            int pw = (p + 3 < S) ? p + 3 : S - 1;   // W row used at iter p+4
            int pv = (p + 4 < S) ? p + 4 : S - 1;   // V row used at iter p+4
            float wf[EPT], vf[EPT];
            #pragma unroll
            for (int e = 0; e < EPT; e++) {
                wf[e] = g_Wt[(size_t)pw * H + base + e * WTH];
                vf[e] = V[(size_t)pv * H + base + e * WTH];
            }

            // consume dec(p-2)
            unsigned d;
            do { d = decv[(p - 2) & (RDEP - 1)]; } while ((d >> 1) != (unsigned)(p - 2));
            const bool  s  = (d & 1);
            const float sm = (float)(d & 1);

            float e0 = 0.f, e1 = 0.f;
            #pragma unroll
            for (int e = 0; e < EPT; e++) {
                a[e] = fmaf(sm, wPrev[e], a[e]);
                h[e] = s ? h1[e] : h[e];
                h1[e] = sigmoidf_fast(a[e] + wC[e]);   // branch s_{p-1}=1
                e0 = fmaf(vC[e], h[e],  e0);
                e1 = fmaf(vC[e], h1[e], e1);
            }
            bfly2(e0, e1);
            publish(p, e0, e1);

            // rotate buffers (unroll lets ptxas rename)
            #pragma unroll
            for (int e = 0; e < EPT; e++) {
                wPrev[e] = wC[e]; wC[e] = wN1[e]; wN1[e] = wN2[e]; wN2[e] = wN3[e]; wN3[e] = wf[e];
                vC[e] = vN1[e]; vN1[e] = vN2[e]; vN2[e] = vN3[e]; vN3[e] = vf[e];
            }
        }
    } else if (wid == NWW) {
        // ================= sender warp =================
        // gather local 8 pairs, sum (fixed order), broadcast E0/E1 to all CTAs
        for (int p = 0; p < S; p++) {
            const unsigned want = (unsigned)p;
            const int r = p & (RDEP - 1);
            uint4 u0, u1, u2, u3, u4, u5, u6, u7;
            for (;;) {
                u0 = lds128v(&wp[r][0]);  u1 = lds128v(&wp[r][2]);
                u2 = lds128v(&wp[r][4]);  u3 = lds128v(&wp[r][6]);
                u4 = lds128v(&wp[r][8]);  u5 = lds128v(&wp[r][10]);
                u6 = lds128v(&wp[r][12]); u7 = lds128v(&wp[r][14]);
                bool ok = (u0.y==want)&(u0.w==want)&(u1.y==want)&(u1.w==want)
                        & (u2.y==want)&(u2.w==want)&(u3.y==want)&(u3.w==want)
                        & (u4.y==want)&(u4.w==want)&(u5.y==want)&(u5.w==want)
                        & (u6.y==want)&(u6.w==want)&(u7.y==want)&(u7.w==want);
                if (ok) break;
            }
            float E0 = ((__uint_as_float(u0.x) + __uint_as_float(u0.z)) +
                        (__uint_as_float(u1.x) + __uint_as_float(u1.z))) +
                       ((__uint_as_float(u2.x) + __uint_as_float(u2.z)) +
                        (__uint_as_float(u3.x) + __uint_as_float(u3.z)));
            float E1 = ((__uint_as_float(u4.x) + __uint_as_float(u4.z)) +
                        (__uint_as_float(u5.x) + __uint_as_float(u5.z))) +
                       ((__uint_as_float(u6.x) + __uint_as_float(u6.z)) +
                        (__uint_as_float(u7.x) + __uint_as_float(u7.z)));
            if (lane < 16) {
                float val = (lane < 8) ? E0 : E1;
                int   slot = ((lane < 8) ? 0 : 8) + (int)rank;
                unsigned long long pk =
                    ((unsigned long long)want << 32) | (unsigned long long)__float_as_uint(val);
                remote_store64(smem_u32(&slots[r][slot]), (unsigned)(lane & 7), pk);
            }
        }
    } else if (wid == NWW + 1) {
        // ================= decider warp =================
        float  bc = b[0],      bn = b[1];
        float2 tc = g_thr2[0], tn = g_thr2[1];
        unsigned sprev = 0;
        const bool xwriter = (rank == 0 && lane == 0);

        for (int i = 0; i < S; i++) {
            const unsigned want = (unsigned)i;
            const int r = i & (RDEP - 1);
            uint4 q0, q1, q2, q3, q4, q5, q6, q7;
            for (;;) {
                q0 = lds128v(&slots[r][0]);  q1 = lds128v(&slots[r][2]);
                q2 = lds128v(&slots[r][4]);  q3 = lds128v(&slots[r][6]);
                q4 = lds128v(&slots[r][8]);  q5 = lds128v(&slots[r][10]);
                q6 = lds128v(&slots[r][12]); q7 = lds128v(&slots[r][14]);
                bool ok = (q0.y==want)&(q0.w==want)&(q1.y==want)&(q1.w==want)
                        & (q2.y==want)&(q2.w==want)&(q3.y==want)&(q3.w==want)
                        & (q4.y==want)&(q4.w==want)&(q5.y==want)&(q5.w==want)
                        & (q6.y==want)&(q6.w==want)&(q7.y==want)&(q7.w==want);
                if (ok) break;
            }
            // fixed-order trees -> identical D0/D1 in every CTA
            float D0 = ((__uint_as_float(q0.x) + __uint_as_float(q0.z)) +
                        (__uint_as_float(q1.x) + __uint_as_float(q1.z))) +
                       ((__uint_as_float(q2.x) + __uint_as_float(q2.z)) +
                        (__uint_as_float(q3.x) + __uint_as_float(q3.z)));
            float D1 = ((__uint_as_float(q4.x) + __uint_as_float(q4.z)) +
                        (__uint_as_float(q5.x) + __uint_as_float(q5.z))) +
                       ((__uint_as_float(q6.x) + __uint_as_float(q6.z)) +
                        (__uint_as_float(q7.x) + __uint_as_float(q7.z)));

            // tiny recurrence tail
            float x = bc + (sprev ? D1 : D0);
            bool  s = thr_cmp(x, tc);
            sprev = (unsigned)s;

            if (lane == 0)
                decv[r] = (want << 1) | (unsigned)s;
            if (xwriter)
                xwv[i] = ((unsigned long long)want << 32) |
                         (unsigned long long)__float_as_uint(x);

            int ip = (i + 2 < S) ? i + 2 : S - 1;
            float bf = b[ip]; float2 tf = g_thr2[ip];
            bc = bn; bn = bf; tc = tn; tn = tf;
        }
    } else {
        // ================= logp/output warp (rank 0, lane 0 only) =================
        if (rank == 0 && lane == 0) {
            float2 tc = g_thr2[0], tn = g_thr2[1];
            double lp = 0.0;
            for (int i = 0; i < S; i++) {
                unsigned long long xv;
                do { xv = xwv[i]; } while ((unsigned)(xv >> 32) != (unsigned)i);
                float x = __uint_as_float((unsigned)xv);
                bool  s = thr_cmp(x, tc);
                out[i] = s ? 1.0f : 0.0f;
                if (i < S - 2)
                    lp -= (double)(s ? softplusf(-x) : softplusf(x));
                int ip = (i + 2 < S) ? i + 2 : S - 1;
                float2 tf = g_thr2[ip];
                tc = tn; tn = tf;
            }
            out[S] = (float)lp;
            for (int k = S + 1; k < out_size; k++) out[k] = 0.f;
        }
    }

    cluster_barrier();   // no CTA exits while peers may still store to its smem
}

// ---------------- launch ----------------
extern "C" void kernel_launch(void* const* d_in, const int* in_sizes, int n_in,
                              void* d_out, int out_size) {
    const float* ctxv = nullptr;
    const float* u    = nullptr;
    const float* W    = nullptr;
    const float* V    = nullptr;
    const float* b    = nullptr;
    const float* c    = nullptr;

    const int szW = (CTX + S) * H;   // 67108864
    const int szV = S * H;           // 33554432
    int n4seen = 0;
    for (int idx = 0; idx < n_in; idx++) {
        int sz = in_sizes[idx];
        const float* p = (const float*)d_in[idx];
        if (sz == szW)       W = p;
        else if (sz == szV)  V = p;
        else if (sz == H)    c = p;
        else if (sz == S) {
            if      (n4seen == 0) ctxv = p;
            else if (n4seen == 1) u    = p;
            else                  b    = p;
            n4seen++;
        }
    }
    if (!ctxv) ctxv = (const float*)d_in[0];
    if (!u)    u    = (const float*)d_in[1];
    if (!W)    W    = (const float*)d_in[2];
    if (!V)    V    = (const float*)d_in[3];
    if (!b)    b    = (const float*)d_in[4];
    if (!c)    c    = (const float*)d_in[5];

    float* out = (float*)d_out;

    gemv_kernel<<<H, 256>>>(W, ctxv, c);
    transpose_kernel<<<dim3(S / 32, H / 32), dim3(32, 8)>>>(W);
    thr_kernel<<<(S + 255) / 256, 256>>>(u);
    nade_kernel<<<CSZ, TPB>>>(V, b, out, out_size);
}

// round 10
// speedup vs baseline: 3.3041x; 1.0058x over previous
#include <cuda_runtime.h>
#include <cstdint>
#include <math.h>

#define H    8192      // DIM_HIDDEN
#define S    4096      // DIM_SOL (steps)
#define CTX  4096      // DIM_CONTEXT
#define CSZ  8         // cluster size
#define NWW  8         // worker warps per CTA (wids 3..10)
#define WTH  256       // worker threads per CTA
#define TPB  352       // sender(0) + decider(1) + logp(2) + 8 workers
#define RDEP 4         // ring depth

// ---------------- device scratch (static, no allocs) ----------------
__device__ float  g_Wt[(size_t)S * H];   // transposed W[:, CTX:]
__device__ float  g_Kt[(size_t)S * H];   // exp(-g_Wt)
__device__ float  g_a0[H];               // a0 = c + W[:, :CTX] @ context
__device__ float2 g_thr2[S];             // (t_hi, t_lo) two-float logit(u_i)

// ---------------- helpers ----------------
__device__ __forceinline__ float sigmoidf_fast(float x) {
    return __fdividef(1.0f, 1.0f + __expf(-x));
}
__device__ __forceinline__ float softplusf(float y) {
    float t = fabsf(y);
    float r = log1pf(__expf(-t));
    return (y > 0.f) ? (y + r) : r;
}
__device__ __forceinline__ unsigned cluster_rank() {
    unsigned r; asm("mov.u32 %0, %%cluster_ctarank;" : "=r"(r)); return r;
}
__device__ __forceinline__ uint32_t smem_u32(const void* p) {
    return (uint32_t)__cvta_generic_to_shared(p);
}
__device__ __forceinline__ void remote_store64(uint32_t laddr, unsigned rank, unsigned long long v) {
    uint32_t raddr;
    asm volatile("mapa.shared::cluster.u32 %0, %1, %2;" : "=r"(raddr) : "r"(laddr), "r"(rank));
    asm volatile("st.relaxed.cluster.shared::cluster.b64 [%0], %1;" :: "r"(raddr), "l"(v) : "memory");
}
__device__ __forceinline__ void cluster_barrier() {
    asm volatile("barrier.cluster.arrive.aligned;" ::: "memory");
    asm volatile("barrier.cluster.wait.aligned;"   ::: "memory");
}
__device__ __forceinline__ uint4 lds128v(const void* p) {
    uint4 r;
    asm volatile("ld.volatile.shared.v4.b32 {%0,%1,%2,%3}, [%4];"
                 : "=r"(r.x), "=r"(r.y), "=r"(r.z), "=r"(r.w) : "r"(smem_u32(p)));
    return r;
}
__device__ __forceinline__ void sts128(void* p, unsigned a, unsigned b, unsigned c, unsigned d) {
    asm volatile("st.shared.v4.b32 [%0], {%1,%2,%3,%4};"
                 :: "r"(smem_u32(p)), "r"(a), "r"(b), "r"(c), "r"(d) : "memory");
}
// interleaved quad warp-sum (workers only; 3T of slack)
__device__ __forceinline__ void bfly4(float& a, float& b, float& c, float& d) {
    #pragma unroll
    for (int o = 16; o > 0; o >>= 1) {
        a += __shfl_xor_sync(0xffffffffu, a, o);
        b += __shfl_xor_sync(0xffffffffu, b, o);
        c += __shfl_xor_sync(0xffffffffu, c, o);
        d += __shfl_xor_sync(0xffffffffu, d, o);
    }
}
__device__ __forceinline__ bool thr_cmp(float x, float2 t) {
    return (x > t.x) || ((x == t.x) && (t.y < 0.f));
}

// ---------------- init kernels ----------------
__global__ void gemv_kernel(const float* __restrict__ W,
                            const float* __restrict__ ctxv,
                            const float* __restrict__ c) {
    __shared__ float sred[256];
    int r = blockIdx.x;
    const float* row = W + (size_t)r * (CTX + S);
    float acc = 0.f;
    for (int k = threadIdx.x; k < CTX; k += 256)
        acc += row[k] * ctxv[k];
    sred[threadIdx.x] = acc;
    __syncthreads();
    for (int off = 128; off > 0; off >>= 1) {
        if (threadIdx.x < off) sred[threadIdx.x] += sred[threadIdx.x + off];
        __syncthreads();
    }
    if (threadIdx.x == 0) g_a0[r] = c[r] + sred[0];
}

__global__ void transpose_kernel(const float* __restrict__ W) {
    __shared__ float tile[32][33];
    int i0 = blockIdx.x * 32;
    int j0 = blockIdx.y * 32;
    int tx = threadIdx.x;
    #pragma unroll
    for (int t = 0; t < 4; t++) {
        int ty = threadIdx.y + t * 8;
        tile[ty][tx] = W[(size_t)(j0 + ty) * (CTX + S) + CTX + i0 + tx];
    }
    __syncthreads();
    #pragma unroll
    for (int t = 0; t < 4; t++) {
        int ty = threadIdx.y + t * 8;
        g_Wt[(size_t)(i0 + ty) * H + j0 + tx] = tile[tx][ty];
    }
}

__global__ void kexp_kernel() {
    size_t n = (size_t)S * H;
    for (size_t i = (size_t)blockIdx.x * blockDim.x + threadIdx.x; i < n;
         i += (size_t)gridDim.x * blockDim.x)
        g_Kt[i] = __expf(-g_Wt[i]);
}

__global__ void thr_kernel(const float* __restrict__ u) {
    int i = blockIdx.x * 256 + threadIdx.x;
    if (i < S) {
        double ud = (double)u[i];
        double t  = log(ud / (1.0 - ud));
        float hi  = (float)t;
        float lo  = (float)(t - (double)hi);
        g_thr2[i] = make_float2(hi, lo);
    }
}

// ---------------- main sequential kernel: 8-CTA cluster ----------------
// wpq[r][w][c] = {tag, z_c0, z_c1, tag} per worker warp w, branch c = s_{p-2}
// slots[r][0..7] = F0 (b=0) per src CTA, [8..15] = F1 (b=1)
__global__ void __cluster_dims__(CSZ, 1, 1) __launch_bounds__(TPB, 1)
nade_kernel(const float* __restrict__ V,
            const float* __restrict__ b,
            float* __restrict__ out,
            int out_size) {
    __shared__ __align__(16) uint4              wpq[RDEP][NWW][2];
    __shared__ __align__(16) unsigned long long slots[RDEP][16];
    __shared__ unsigned int       dec[RDEP];
    __shared__ unsigned long long xw[S];

    const unsigned rank = cluster_rank();
    const int tid  = threadIdx.x;
    const int wid  = tid >> 5;
    const int lane = tid & 31;

    for (int k = tid; k < RDEP * NWW * 2; k += TPB)
        ((uint4*)wpq)[k] = make_uint4(0xFFFFFFFFu, 0, 0, 0xFFFFFFFFu);
    for (int k = tid; k < RDEP * 16; k += TPB)
        ((unsigned long long*)slots)[k] = 0xFFFFFFFF00000000ULL;
    if (tid < RDEP) dec[tid] = 0xFFFFFFFFu;
    for (int k = tid; k < S; k += TPB)
        xw[k] = 0xFFFFFFFF00000000ULL;
    __syncthreads();
    cluster_barrier();

    volatile unsigned int*       decv = dec;
    volatile unsigned long long* xwv  = xw;

    if (wid >= 3) {
        // ================= worker warps (wids 3..10) =================
        const int w    = wid - 3;
        const int wtid = tid - 96;                       // 0..255
        const int j0   = (int)rank * (WTH * 4) + wtid * 4;

        float a0v[4], a[4];
        float s00[4], s01[4], s10[4], s11[4];            // sig quad (current step)
        float4 w8[8], k8[8], v8[8];                      // register rings

        auto publish = [&](int p, float z00, float z01, float z10, float z11) {
            bfly4(z00, z01, z10, z11);
            if (lane == 0) {
                unsigned tg = (unsigned)p;
                const int r = p & (RDEP - 1);
                sts128(&wpq[r][w][0], tg, __float_as_uint(z00), __float_as_uint(z01), tg);
                sts128(&wpq[r][w][1], tg, __float_as_uint(z10), __float_as_uint(z11), tg);
            }
        };

        // ---- prologue: quads 0,1,2; state for iter 3 ----
        {
            float4 av = *(const float4*)&g_a0[j0];
            a0v[0]=av.x; a0v[1]=av.y; a0v[2]=av.z; a0v[3]=av.w;
            float4 w0 = *(const float4*)&g_Wt[j0];
            float4 w1 = *(const float4*)&g_Wt[(size_t)1 * H + j0];
            float4 v0 = *(const float4*)&V[j0];
            float4 v1 = *(const float4*)&V[(size_t)1 * H + j0];
            float4 v2 = *(const float4*)&V[(size_t)2 * H + j0];
            const float w0a[4] = {w0.x, w0.y, w0.z, w0.w};
            const float w1a[4] = {w1.x, w1.y, w1.z, w1.w};
            const float v0a[4] = {v0.x, v0.y, v0.z, v0.w};
            const float v1a[4] = {v1.x, v1.y, v1.z, v1.w};
            const float v2a[4] = {v2.x, v2.y, v2.z, v2.w};

            float z = 0.f, zA = 0.f, zB = 0.f;
            float q00 = 0.f, q01 = 0.f, q10 = 0.f, q11 = 0.f;
            #pragma unroll
            for (int e = 0; e < 4; e++) {
                a[e] = a0v[e];
                float h0 = sigmoidf_fast(a[e]);
                s00[e] = h0;                               // sigma(a0)
                s10[e] = sigmoidf_fast(a[e] + w0a[e]);     // sigma(a0+W0)
                s01[e] = sigmoidf_fast(a[e] + w1a[e]);     // sigma(a0+W1)
                s11[e] = sigmoidf_fast(a[e] + w0a[e] + w1a[e]);
                z  = fmaf(v0a[e], h0, z);
                zA = fmaf(v1a[e], h0, zA);
                zB = fmaf(v1a[e], s10[e], zB);
                q00 = fmaf(v2a[e], s00[e], q00);
                q01 = fmaf(v2a[e], s01[e], q01);
                q10 = fmaf(v2a[e], s10[e], q10);
                q11 = fmaf(v2a[e], s11[e], q11);
            }
            publish(0, z,  z,  z,  z);
            publish(1, zA, zB, zA, zB);
            publish(2, q00, q01, q10, q11);

            // preload ring slots 0..6 with rows 0..6
            #pragma unroll
            for (int rI = 0; rI < 7; rI++) {
                w8[rI] = *(const float4*)&g_Wt[(size_t)rI * H + j0];
                k8[rI] = *(const float4*)&g_Kt[(size_t)rI * H + j0];
                v8[rI] = *(const float4*)&V[(size_t)rI * H + j0];
            }
        }

        // ---- main loop: iters p = 3 .. 3+4096 (padded for unroll-8 alignment) ----
        #pragma unroll 8
        for (int p = 3; p < 3 + 4096; p++) {
            // prefetch row p+4 into slot (p+4)&7
            int pf = (p + 4 < S) ? p + 4 : S - 1;
            w8[(p + 4) & 7] = *(const float4*)&g_Wt[(size_t)pf * H + j0];
            k8[(p + 4) & 7] = *(const float4*)&g_Kt[(size_t)pf * H + j0];
            v8[(p + 4) & 7] = *(const float4*)&V[(size_t)pf * H + j0];

            // pre-dec: xpre = exp(-(A_{p-4} + W_{p-1}))
            float4 wm1 = w8[(p - 1) & 7];
            float xpre[4];
            xpre[0] = __expf(-(a[0] + wm1.x));
            xpre[1] = __expf(-(a[1] + wm1.y));
            xpre[2] = __expf(-(a[2] + wm1.z));
            xpre[3] = __expf(-(a[3] + wm1.w));

            // wait dec(p-3)
            unsigned d;
            do { d = decv[(p - 3) & (RDEP - 1)]; } while ((d >> 1) != (unsigned)(p - 3));
            const bool  s  = (d & 1);
            const float sm = (float)(d & 1);

            float4 wm3 = w8[(p - 3) & 7];
            float4 km3 = k8[(p - 3) & 7];
            float4 km2 = k8[(p - 2) & 7];
            float4 vp  = v8[p & 7];
            const float wm3a[4] = {wm3.x, wm3.y, wm3.z, wm3.w};
            const float km3a[4] = {km3.x, km3.y, km3.z, km3.w};
            const float km2a[4] = {km2.x, km2.y, km2.z, km2.w};
            const float vpa[4]  = {vp.x,  vp.y,  vp.z,  vp.w};

            float z00 = 0.f, z01 = 0.f, z10 = 0.f, z11 = 0.f;
            #pragma unroll
            for (int e = 0; e < 4; e++) {
                a[e] = fmaf(sm, wm3a[e], a[e]);            // commit s_{p-3}
                float Xi  = s ? xpre[e] * km3a[e] : xpre[e];  // exp(-(A_{p-3}+W_{p-1}))
                float n00 = s ? s10[e] : s00[e];           // sigma(A_{p-3}+c*W_{p-2}), c=0
                float n10 = s ? s11[e] : s01[e];           // c=1
                float n01 = __fdividef(1.f, 1.f + Xi);                 // c=0,b=1
                float n11 = __fdividef(1.f, 1.f + Xi * km2a[e]);       // c=1,b=1
                z00 = fmaf(vpa[e], n00, z00);
                z01 = fmaf(vpa[e], n01, z01);
                z10 = fmaf(vpa[e], n10, z10);
                z11 = fmaf(vpa[e], n11, z11);
                s00[e] = n00; s01[e] = n01; s10[e] = n10; s11[e] = n11;
            }
            if (p < S) publish(p, z00, z01, z10, z11);
        }
    } else if (wid == 0) {
        // ================= sender warp =================
        for (int p = 0; p < S; p++) {
            const unsigned want = (unsigned)p;
            const int r = p & (RDEP - 1);
            uint4 u0[NWW], u1[NWW];
            for (;;) {
                bool ok = true;
                #pragma unroll
                for (int w = 0; w < NWW; w++) {
                    u0[w] = lds128v(&wpq[r][w][0]);
                    u1[w] = lds128v(&wpq[r][w][1]);
                    ok &= (u0[w].x == want) & (u0[w].w == want)
                        & (u1[w].x == want) & (u1[w].w == want);
                }
                if (ok) break;
            }
            unsigned c = 0;
            if (p >= 2) {
                unsigned d;
                do { d = decv[(p - 2) & (RDEP - 1)]; } while ((d >> 1) != (unsigned)(p - 2));
                c = d & 1;
            }
            // c-select, then fixed-order trees over 8 warps
            float f0[NWW], f1[NWW];
            #pragma unroll
            for (int w = 0; w < NWW; w++) {
                f0[w] = __uint_as_float(c ? u1[w].y : u0[w].y);
                f1[w] = __uint_as_float(c ? u1[w].z : u0[w].z);
            }
            float F0 = ((f0[0] + f0[1]) + (f0[2] + f0[3])) + ((f0[4] + f0[5]) + (f0[6] + f0[7]));
            float F1 = ((f1[0] + f1[1]) + (f1[2] + f1[3])) + ((f1[4] + f1[5]) + (f1[6] + f1[7]));
            if (lane < 16) {
                float val = (lane < 8) ? F0 : F1;
                int   slot = ((lane < 8) ? 0 : 8) + (int)rank;
                unsigned long long pk =
                    ((unsigned long long)want << 32) | (unsigned long long)__float_as_uint(val);
                remote_store64(smem_u32(&slots[r][slot]), (unsigned)(lane & 7), pk);
            }
        }
    } else if (wid == 1) {
        // ================= decider warp =================
        float  bc = b[0],      bn = b[1];
        float2 tc = g_thr2[0], tn = g_thr2[1];
        unsigned sprev = 0;
        const bool xwriter = (rank == 0 && lane == 0);

        for (int i = 0; i < S; i++) {
            const unsigned want = (unsigned)i;
            const int r = i & (RDEP - 1);
            uint4 q0, q1, q2, q3, q4, q5, q6, q7;
            for (;;) {
                q0 = lds128v(&slots[r][0]);  q1 = lds128v(&slots[r][2]);
                q2 = lds128v(&slots[r][4]);  q3 = lds128v(&slots[r][6]);
                q4 = lds128v(&slots[r][8]);  q5 = lds128v(&slots[r][10]);
                q6 = lds128v(&slots[r][12]); q7 = lds128v(&slots[r][14]);
                bool ok = (q0.y==want)&(q0.w==want)&(q1.y==want)&(q1.w==want)
                        & (q2.y==want)&(q2.w==want)&(q3.y==want)&(q3.w==want)
                        & (q4.y==want)&(q4.w==want)&(q5.y==want)&(q5.w==want)
                        & (q6.y==want)&(q6.w==want)&(q7.y==want)&(q7.w==want);
                if (ok) break;
            }
            float D0 = ((__uint_as_float(q0.x) + __uint_as_float(q0.z)) +
                        (__uint_as_float(q1.x) + __uint_as_float(q1.z))) +
                       ((__uint_as_float(q2.x) + __uint_as_float(q2.z)) +
                        (__uint_as_float(q3.x) + __uint_as_float(q3.z)));
            float D1 = ((__uint_as_float(q4.x) + __uint_as_float(q4.z)) +
                        (__uint_as_float(q5.x) + __uint_as_float(q5.z))) +
                       ((__uint_as_float(q6.x) + __uint_as_float(q6.z)) +
                        (__uint_as_float(q7.x) + __uint_as_float(q7.z)));

            float x = bc + (sprev ? D1 : D0);
            bool  s = thr_cmp(x, tc);
            sprev = (unsigned)s;

            if (lane == 0)
                decv[r] = (want << 1) | (unsigned)s;
            if (xwriter)
                xwv[i] = ((unsigned long long)want << 32) |
                         (unsigned long long)__float_as_uint(x);

            int ip = (i + 2 < S) ? i + 2 : S - 1;
            float bf = b[ip]; float2 tf = g_thr2[ip];
            bc = bn; bn = bf; tc = tn; tn = tf;
        }
    } else {
        // ================= logp/output warp (wid 2; rank 0, lane 0) =================
        if (rank == 0 && lane == 0) {
            float2 tc = g_thr2[0], tn = g_thr2[1];
            double lp = 0.0;
            for (int i = 0; i < S; i++) {
                unsigned long long xv;
                do { xv = xwv[i]; } while ((unsigned)(xv >> 32) != (unsigned)i);
                float x = __uint_as_float((unsigned)xv);
                bool  s = thr_cmp(x, tc);
                out[i] = s ? 1.0f : 0.0f;
                if (i < S - 2)
                    lp -= (double)(s ? softplusf(-x) : softplusf(x));
                int ip = (i + 2 < S) ? i + 2 : S - 1;
                float2 tf = g_thr2[ip];
                tc = tn; tn = tf;
            }
            out[S] = (float)lp;
            for (int k = S + 1; k < out_size; k++) out[k] = 0.f;
        }
    }

    cluster_barrier();   // no CTA exits while peers may still store to its smem
}

// ---------------- launch ----------------
extern "C" void kernel_launch(void* const* d_in, const int* in_sizes, int n_in,
                              void* d_out, int out_size) {
    const float* ctxv = nullptr;
    const float* u    = nullptr;
    const float* W    = nullptr;
    const float* V    = nullptr;
    const float* b    = nullptr;
    const float* c    = nullptr;

    const int szW = (CTX + S) * H;   // 67108864
    const int szV = S * H;           // 33554432
    int n4seen = 0;
    for (int idx = 0; idx < n_in; idx++) {
        int sz = in_sizes[idx];
        const float* p = (const float*)d_in[idx];
        if (sz == szW)       W = p;
        else if (sz == szV)  V = p;
        else if (sz == H)    c = p;
        else if (sz == S) {
            if      (n4seen == 0) ctxv = p;
            else if (n4seen == 1) u    = p;
            else                  b    = p;
            n4seen++;
        }
    }
    if (!ctxv) ctxv = (const float*)d_in[0];
    if (!u)    u    = (const float*)d_in[1];
    if (!W)    W    = (const float*)d_in[2];
    if (!V)    V    = (const float*)d_in[3];
    if (!b)    b    = (const float*)d_in[4];
    if (!c)    c    = (const float*)d_in[5];

    float* out = (float*)d_out;

    gemv_kernel<<<H, 256>>>(W, ctxv, c);
    transpose_kernel<<<dim3(S / 32, H / 32), dim3(32, 8)>>>(W);
    kexp_kernel<<<1024, 256>>>();
    thr_kernel<<<(S + 255) / 256, 256>>>(u);
    nade_kernel<<<CSZ, TPB>>>(V, b, out, out_size);
}